// round 16
// baseline (speedup 1.0000x reference)
#include <cuda_runtime.h>
#include <math.h>
#include <stdint.h>

// ---------------- problem constants ----------------
#define BB 32
#define LL 1024
#define DD 256
#define HH 4
#define EE 64
#define NBAND 308          // f = 205..512
#define F0 205
#define TOPK 34

// ---------------- scratch layout (floats) ----------------
constexpr size_t SZ   = (size_t)BB * LL * DD;        // 8388608
constexpr size_t SPEC = (size_t)BB * DD * 640;       // 5242880 (8192 x 640)

constexpr size_t O_Q    = 0;
constexpr size_t O_K    = O_Q + SZ;
constexpr size_t O_V    = O_K + SZ;
constexpr size_t O_KT   = O_V + SZ;
constexpr size_t O_VT   = O_KT + SZ;
constexpr size_t O_TR   = O_VT + SZ;       // Qt
constexpr size_t O_SPQ  = O_TR + SZ;
constexpr size_t O_SPK  = O_SPQ + SPEC;
constexpr size_t O_SPV  = O_SPK + SPEC;
constexpr size_t O_QS   = O_SPV + SPEC;
constexpr size_t O_VS   = O_QS + SZ;
constexpr size_t O_CSP  = O_VS + SZ;       // ctx spatial (B,L,D)
constexpr size_t O_AGG  = O_CSP + SZ;      // time agg (B,D,L)
constexpr size_t O_CTX  = O_AGG + SZ;      // mixed context (B,L,D)
constexpr size_t O_T1   = O_CTX + SZ;      // also corr partials scratch
constexpr size_t O_H    = O_T1 + SZ;
constexpr size_t O_G1   = O_H + SZ;
constexpr size_t O_F    = O_G1 + SZ;
constexpr size_t O_MV   = O_F + SZ;                 // mean_value 32x1024
constexpr size_t O_W    = O_MV + (size_t)BB * LL;   // weights 32x64
constexpr size_t TOTAL  = O_W + (size_t)BB * 64;

__device__ float g_scr[TOTAL + 1024];
__device__ int   g_idx[64];

// ---------------- cp.async helpers ----------------
__device__ __forceinline__ void cpa16(uint32_t saddr, const void* gptr) {
    asm volatile("cp.async.cg.shared.global [%0], [%1], 16;" :: "r"(saddr), "l"(gptr));
}
__device__ __forceinline__ void cpa_commit() {
    asm volatile("cp.async.commit_group;");
}
template<int N>
__device__ __forceinline__ void cpa_wait() {
    asm volatile("cp.async.wait_group %0;" :: "n"(N));
}

// ---------------- tf32 mma helpers ----------------
__device__ __forceinline__ uint32_t f2tf(float f) {
    return __float_as_uint(f);   // hardware tf32 mma truncates to top 19 bits
}
__device__ __forceinline__ void mma_tf32(float* d, const uint32_t* a, const uint32_t* b) {
    asm volatile(
        "mma.sync.aligned.m16n8k8.row.col.f32.tf32.tf32.f32 "
        "{%0,%1,%2,%3}, {%4,%5,%6,%7}, {%8,%9}, {%0,%1,%2,%3};"
        : "+f"(d[0]), "+f"(d[1]), "+f"(d[2]), "+f"(d[3])
        : "r"(a[0]), "r"(a[1]), "r"(a[2]), "r"(a[3]), "r"(b[0]), "r"(b[1]));
}

// ---------------- fast exp on the FMA pipe ----------------
__device__ __forceinline__ float fexp(float x) {
    x = fmaxf(x, -87.0f);
    float z = x * 1.4426950408889634f;
    float r = rintf(z);
    float f = z - r;
    float p = 1.5403530e-4f;
    p = fmaf(p, f, 1.3333558e-3f);
    p = fmaf(p, f, 9.6181291e-3f);
    p = fmaf(p, f, 5.5504109e-2f);
    p = fmaf(p, f, 2.4022651e-1f);
    p = fmaf(p, f, 6.9314718e-1f);
    p = fmaf(p, f, 1.0f);
    int e = (int)r;
    return __int_as_float((e + 127) << 23) * p;
}

// ---------------- 1024-pt radix-4 FFT, register-resident ----------------
__device__ __forceinline__ int rev4_10(int l) {
    int b = __brev((unsigned)l) >> 22;
    return ((b & 0x155) << 1) | ((b & 0x2AA) >> 1);
}
__device__ __forceinline__ float2 cmul(float2 a, float2 b) {
    return make_float2(a.x * b.x - a.y * b.y, a.x * b.y + a.y * b.x);
}
__device__ __forceinline__ int IDX(int p) { return p + (p >> 5); }   // skew

template<bool INV>
__device__ __forceinline__ void bf4(float2& A, float2& B, float2& C, float2& D,
                                    float2 w1, float2 w2, float2 w3)
{
    float2 b = cmul(B, w1), c = cmul(C, w2), d = cmul(D, w3);
    float2 t0 = make_float2(A.x + c.x, A.y + c.y);
    float2 t1 = make_float2(A.x - c.x, A.y - c.y);
    float2 t2 = make_float2(b.x + d.x, b.y + d.y);
    float2 t3 = make_float2(b.x - d.x, b.y - d.y);
    A = make_float2(t0.x + t2.x, t0.y + t2.y);
    C = make_float2(t0.x - t2.x, t0.y - t2.y);
    if (!INV) {
        B = make_float2(t1.x + t3.y, t1.y - t3.x);
        D = make_float2(t1.x - t3.y, t1.y + t3.x);
    } else {
        B = make_float2(t1.x - t3.y, t1.y + t3.x);
        D = make_float2(t1.x + t3.y, t1.y - t3.x);
    }
}

// 5 radix-4 stages; sb pre-filled in digit-reversed (skewed) order.
// th = 0..63 (thread-in-row). Results left in r[16]:
//   r[4*i + k] = X[4*th + i + 256*k].
template<bool INV>
__device__ __forceinline__ void fft_reg(float2* sb, const float2* tw, int th,
                                        float2 (&r)[16])
{
    // phase A: 16 consecutive elements; stages 0 (unit twiddles) and 1
#pragma unroll
    for (int i = 0; i < 16; i++) r[i] = sb[IDX(th * 16 + i)];
    const float2 one = make_float2(1.f, 0.f);
#pragma unroll
    for (int a = 0; a < 4; a++)
        bf4<INV>(r[4*a], r[4*a+1], r[4*a+2], r[4*a+3], one, one, one);
#pragma unroll
    for (int pos = 0; pos < 4; pos++) {
        int e = pos << 6;
        bf4<INV>(r[pos], r[pos+4], r[pos+8], r[pos+12], tw[e], tw[2*e], tw[3*e]);
    }
#pragma unroll
    for (int i = 0; i < 16; i++) sb[IDX(th * 16 + i)] = r[i];
    __syncthreads();

    // phase B: ownership p = 256c + 16m + rb; stages 2 and 3
    const int c = th >> 4, rb = th & 15;
    const int pb = 256 * c + rb;
#pragma unroll
    for (int m = 0; m < 16; m++) r[m] = sb[IDX(pb + 16 * m)];
    {
        int e = rb << 4;
        float2 w1 = tw[e], w2 = tw[2*e], w3 = tw[3*e];
#pragma unroll
        for (int a = 0; a < 4; a++)
            bf4<INV>(r[4*a], r[4*a+1], r[4*a+2], r[4*a+3], w1, w2, w3);
    }
#pragma unroll
    for (int m0 = 0; m0 < 4; m0++) {
        int e = 64 * m0 + 4 * rb;
        bf4<INV>(r[m0], r[m0+4], r[m0+8], r[m0+12], tw[e], tw[2*e], tw[3*e]);
    }
#pragma unroll
    for (int m = 0; m < 16; m++) sb[IDX(pb + 16 * m)] = r[m];
    __syncthreads();

    // phase C: ownership q = 4*th + i, elements q + 256k; stage 4
#pragma unroll
    for (int i = 0; i < 4; i++)
#pragma unroll
        for (int k = 0; k < 4; k++)
            r[4*i + k] = sb[IDX(4*th + i + 256*k)];
#pragma unroll
    for (int i = 0; i < 4; i++) {
        int e = 4*th + i;
        bf4<INV>(r[4*i], r[4*i+1], r[4*i+2], r[4*i+3], tw[e], tw[2*e], tw[3*e]);
    }
}

// Forward FFT: 8 rows per block, 512 threads (64/row), dynamic smem.
__global__ void __launch_bounds__(512) fftfwd_k(
    const float* __restrict__ in, float* __restrict__ spec)
{
    extern __shared__ float2 fsm[];
    float2* tw = fsm;               // 768
    float2* s  = fsm + 768;         // 8 * 1056
    const int th = threadIdx.x & 63;
    const int rr = threadIdx.x >> 6;
    const int row = blockIdx.x * 8 + rr;
    const float* xr = in + (size_t)row * LL;
    float2* sb = s + rr * 1056;

    for (int k = threadIdx.x; k < 768; k += 512) {
        float ang = -6.283185307179586f * (float)k / 1024.0f;
        tw[k] = make_float2(cosf(ang), sinf(ang));
    }
    for (int l = th; l < 1024; l += 64)
        sb[IDX(rev4_10(l))] = make_float2(xr[l], 0.f);
    __syncthreads();

    float2 r[16];
    fft_reg<false>(sb, tw, th, r);

#pragma unroll
    for (int i = 0; i < 4; i++)
#pragma unroll
        for (int k = 0; k < 4; k++) {
            int idx = 4*th + i + 256*k;
            if (idx >= F0 && idx <= 512) {
                spec[(size_t)row * 640 + idx - F0]       = r[4*i + k].x;
                spec[(size_t)row * 640 + 320 + idx - F0] = r[4*i + k].y;
            }
        }
}

// Inverse FFT: 8 rows per block, 512 threads (64/row), dynamic smem.
__global__ void __launch_bounds__(512) fftinv_k(
    const float* __restrict__ spec, float* __restrict__ outr)
{
    extern __shared__ float2 fsm[];
    float2* tw = fsm;
    float2* s  = fsm + 768;
    const int th = threadIdx.x & 63;
    const int rr = threadIdx.x >> 6;
    const int row = blockIdx.x * 8 + rr;
    const float* sp = spec + (size_t)row * 640;
    float2* sb = s + rr * 1056;

    for (int k = threadIdx.x; k < 768; k += 512) {
        float ang = 6.283185307179586f * (float)k / 1024.0f;
        tw[k] = make_float2(cosf(ang), sinf(ang));
    }
    for (int l = th; l < 1024; l += 64) {
        float2 v = make_float2(0.f, 0.f);
        if (l >= F0 && l <= 512) {
            v.x = sp[l - F0];
            v.y = sp[320 + l - F0];
        } else if (l >= 513 && l <= 1024 - F0) {
            int f = 1024 - l;
            v.x = sp[f - F0];
            v.y = -sp[320 + f - F0];
        }
        sb[IDX(rev4_10(l))] = v;
    }
    __syncthreads();

    float2 r[16];
    fft_reg<true>(sb, tw, th, r);

    const float sc = 1.0f / 1024.0f;
#pragma unroll
    for (int k = 0; k < 4; k++) {
        float4 o;
        o.x = r[0 + k].x * sc;
        o.y = r[4 + k].x * sc;
        o.z = r[8 + k].x * sc;
        o.w = r[12 + k].x * sc;
        *(float4*)&outr[(size_t)row * LL + 4*th + 256*k] = o;
    }
}

// ---------------- tf32 tensor-core GEMM, 128x128 (R11 proven) --------------
// EPI: 1 +bias, 2 +bias+res, 3 +bias then gelu(erf)
template<int EPI>
__global__ void __launch_bounds__(256) gemm_tc(
    const float* __restrict__ A, const float* __restrict__ Bw,
    const float* __restrict__ bias, const float* __restrict__ res,
    float* __restrict__ C, int M, int N, int K)
{
    __shared__ float As[2][128][20];
    __shared__ float Bs[2][16][136];
    const int bn = blockIdx.x * 128;
    const int bm = blockIdx.y * 128;
    const int tid = threadIdx.x, wid = tid >> 5, lane = tid & 31;
    const int grp = lane >> 2, tig = lane & 3;
    const int wm = (wid & 3) * 32, wn = (wid >> 2) * 64;

    const uint32_t asb = (uint32_t)__cvta_generic_to_shared(&As[0][0][0]);
    const uint32_t bsb = (uint32_t)__cvta_generic_to_shared(&Bs[0][0][0]);
    const int T = K >> 4;

    auto loadA = [&](int st, int k0) {
#pragma unroll
        for (int u = 0; u < 2; u++) {
            int c = tid + u * 256;
            int row = c >> 2, kq = (c & 3) * 4;
            cpa16(asb + (uint32_t)(st * 128 * 20 + row * 20 + kq) * 4,
                  &A[(size_t)(bm + row) * K + k0 + kq]);
        }
    };
    auto loadB = [&](int st, int k0) {
#pragma unroll
        for (int u = 0; u < 2; u++) {
            int c = tid + u * 256;
            int r = c >> 5, col = (c & 31) * 4;
            cpa16(bsb + (uint32_t)(st * 16 * 136 + r * 136 + col) * 4,
                  &Bw[(size_t)(k0 + r) * N + bn + col]);
        }
    };

    loadA(0, 0); loadB(0, 0); cpa_commit();

    float d[2][8][4];
#pragma unroll
    for (int am = 0; am < 2; am++)
#pragma unroll
        for (int an = 0; an < 8; an++)
#pragma unroll
            for (int q = 0; q < 4; q++) d[am][an][q] = 0.f;

    for (int kt = 0; kt < T; kt++) {
        if (kt + 1 < T) {
            loadA((kt + 1) & 1, (kt + 1) << 4);
            loadB((kt + 1) & 1, (kt + 1) << 4);
            cpa_commit();
            cpa_wait<1>();
        } else {
            cpa_wait<0>();
        }
        __syncthreads();
        const int st = kt & 1;
#pragma unroll
        for (int k8 = 0; k8 < 16; k8 += 8) {
            uint32_t a[2][4];
#pragma unroll
            for (int am = 0; am < 2; am++) {
                int mr = wm + am * 16;
                a[am][0] = f2tf(As[st][mr + grp][k8 + tig]);
                a[am][1] = f2tf(As[st][mr + grp + 8][k8 + tig]);
                a[am][2] = f2tf(As[st][mr + grp][k8 + tig + 4]);
                a[am][3] = f2tf(As[st][mr + grp + 8][k8 + tig + 4]);
            }
#pragma unroll
            for (int an = 0; an < 8; an++) {
                uint32_t b[2];
                b[0] = f2tf(Bs[st][k8 + tig][wn + an * 8 + grp]);
                b[1] = f2tf(Bs[st][k8 + tig + 4][wn + an * 8 + grp]);
                mma_tf32(d[0][an], a[0], b);
                mma_tf32(d[1][an], a[1], b);
            }
        }
        __syncthreads();
    }

#pragma unroll
    for (int am = 0; am < 2; am++) {
        int row0 = bm + wm + am * 16 + grp;
#pragma unroll
        for (int an = 0; an < 8; an++) {
            int col = bn + wn + an * 8 + 2 * tig;
            float o0 = d[am][an][0], o1 = d[am][an][1];
            float o2 = d[am][an][2], o3 = d[am][an][3];
            float2 bv = *(const float2*)&bias[col];
            o0 += bv.x; o1 += bv.y; o2 += bv.x; o3 += bv.y;
            if (EPI == 2) {
                float2 r0v = *(const float2*)&res[(size_t)row0 * N + col];
                float2 r1v = *(const float2*)&res[(size_t)(row0 + 8) * N + col];
                o0 += r0v.x; o1 += r0v.y; o2 += r1v.x; o3 += r1v.y;
            }
            if (EPI == 3) {
                o0 = o0 * 0.5f * (1.0f + erff(o0 * 0.70710678118654752f));
                o1 = o1 * 0.5f * (1.0f + erff(o1 * 0.70710678118654752f));
                o2 = o2 * 0.5f * (1.0f + erff(o2 * 0.70710678118654752f));
                o3 = o3 * 0.5f * (1.0f + erff(o3 * 0.70710678118654752f));
            }
            float2 w0; w0.x = o0; w0.y = o1;
            float2 w1; w1.x = o2; w1.y = o3;
            *(float2*)&C[(size_t)row0 * N + col] = w0;
            *(float2*)&C[(size_t)(row0 + 8) * N + col] = w1;
        }
    }
}

// ---------------- fused triple transpose: (B,L,D) -> (B,D,L) x3 ----------
__global__ void tr3_k(const float* __restrict__ sK, const float* __restrict__ sV,
                      const float* __restrict__ sQ,
                      float* __restrict__ dK, float* __restrict__ dV,
                      float* __restrict__ dQ)
{
    __shared__ float tile[32][33];
    int z = blockIdx.z;
    int tsr = z >> 5, b = z & 31;
    const float* I = (tsr == 0 ? sK : tsr == 1 ? sV : sQ) + (size_t)b * LL * DD;
    float* O = (tsr == 0 ? dK : tsr == 1 ? dV : dQ) + (size_t)b * LL * DD;
    int c0 = blockIdx.x * 32, r0 = blockIdx.y * 32;
    int x = threadIdx.x, y = threadIdx.y;
#pragma unroll
    for (int i = 0; i < 32; i += 8)
        tile[y + i][x] = I[(size_t)(r0 + y + i) * DD + c0 + x];
    __syncthreads();
#pragma unroll
    for (int i = 0; i < 32; i += 8)
        O[(size_t)(c0 + y + i) * LL + r0 + x] = tile[x][y + i];
}

// ---------------- corr spectrum sum, pass 1 ----------
__global__ void __launch_bounds__(256) corr_part_k(
    const float* __restrict__ Qs, const float* __restrict__ Ks,
    float* __restrict__ Spart)
{
    const int g = blockIdx.x, b = blockIdx.y;
    const int t = threadIdx.x;
    const int j0 = t, j1 = t + 256;
    float re0 = 0.f, im0 = 0.f, re1 = 0.f, im1 = 0.f;
    size_t base = ((size_t)(b * 256 + g * 32)) * 640;
    for (int r = 0; r < 32; r++) {
        size_t row = base + (size_t)r * 640;
        float qr = Qs[row + j0], qi = Qs[row + 320 + j0];
        float kr = Ks[row + j0], ki = Ks[row + 320 + j0];
        re0 += qr * kr + qi * ki;
        im0 += qi * kr - qr * ki;
        if (j1 < NBAND) {
            qr = Qs[row + j1]; qi = Qs[row + 320 + j1];
            kr = Ks[row + j1]; ki = Ks[row + 320 + j1];
            re1 += qr * kr + qi * ki;
            im1 += qi * kr - qr * ki;
        }
    }
    size_t o = (size_t)(b * 8 + g) * 640;
    Spart[o + j0] = re0;
    Spart[o + 320 + j0] = im0;
    if (j1 < NBAND) {
        Spart[o + j1] = re1;
        Spart[o + 320 + j1] = im1;
    } else if (j1 < 320) {
        Spart[o + j1] = 0.f;
        Spart[o + 320 + j1] = 0.f;
    }
}

// ---------------- mean_value (folds 8-partial reduction in) ----------------
__global__ void __launch_bounds__(256) meanv_k(
    const float* __restrict__ Spart, float* __restrict__ mv)
{
    int b = blockIdx.x, t = threadIdx.x;
    __shared__ float sre[NBAND], sim[NBAND], tbl[1024];
    for (int j = t; j < NBAND; j += 256) {
        float ar = 0.f, ai = 0.f;
#pragma unroll
        for (int g = 0; g < 8; g++) {
            size_t o = (size_t)(b * 8 + g) * 640;
            ar += Spart[o + j];
            ai += Spart[o + 320 + j];
        }
        sre[j] = ar;
        sim[j] = ai;
    }
    for (int m = t; m < 1024; m += 256)
        tbl[m] = cosf(6.283185307179586f * (float)m / 1024.0f);
    __syncthreads();
    int tt = blockIdx.y * 256 + t;
    float acc = sre[NBAND - 1] * ((tt & 1) ? -1.f : 1.f);
    for (int j = 0; j < NBAND - 1; j++) {
        int f = F0 + j;
        int m = (f * tt) & 1023;
        float c = tbl[m];
        float s = tbl[(m + 768) & 1023];
        acc += 2.f * (sre[j] * c - sim[j] * s);
    }
    mv[(size_t)b * 1024 + tt] = acc * (1.0f / (256.0f * 1024.0f));
}

// ---------------- top-k over batch-mean + per-batch softmax weights --------
__global__ void topk_k(const float* __restrict__ mv, int* __restrict__ idxout,
                       float* __restrict__ w)
{
    int t = threadIdx.x;  // 1024
    __shared__ float vals[1024];
    __shared__ float rv[1024];
    __shared__ int   ri[1024];
    __shared__ int   is[TOPK];
    float g = 0.f;
    for (int b = 0; b < BB; b++) g += mv[(size_t)b * 1024 + t];
    vals[t] = g;
    __syncthreads();
    for (int k = 0; k < TOPK; k++) {
        rv[t] = vals[t]; ri[t] = t; __syncthreads();
        for (int s = 512; s > 0; s >>= 1) {
            if (t < s) {
                if (rv[t + s] > rv[t] || (rv[t + s] == rv[t] && ri[t + s] < ri[t])) {
                    rv[t] = rv[t + s]; ri[t] = ri[t + s];
                }
            }
            __syncthreads();
        }
        if (t == 0) { idxout[k] = ri[0]; is[k] = ri[0]; vals[ri[0]] = -3.4e38f; }
        __syncthreads();
    }
    // weights: warp b handles batch b (32 warps = 32 batches)
    int b = t >> 5, lane = t & 31;
    float v0 = mv[(size_t)b * 1024 + is[lane < TOPK ? lane : 0]];
    if (lane >= TOPK) v0 = -3.4e38f;
    float v1 = (lane + 32 < TOPK) ? mv[(size_t)b * 1024 + is[lane + 32]] : -3.4e38f;
    float mx = fmaxf(v0, v1);
#pragma unroll
    for (int off = 16; off > 0; off >>= 1)
        mx = fmaxf(mx, __shfl_xor_sync(0xffffffffu, mx, off));
    float e0 = (lane < TOPK) ? expf(v0 - mx) : 0.f;
    float e1 = (lane + 32 < TOPK) ? expf(v1 - mx) : 0.f;
    float sm = e0 + e1;
#pragma unroll
    for (int off = 16; off > 0; off >>= 1)
        sm += __shfl_xor_sync(0xffffffffu, sm, off);
    float inv = 1.0f / sm;
    if (lane < TOPK) w[(size_t)b * 64 + lane] = e0 * inv;
    if (lane + 32 < TOPK) w[(size_t)b * 64 + lane + 32] = e1 * inv;
}

// ---------------- flash attention, tf32 tensor cores, 2 m-atoms/warp -------
__global__ void __launch_bounds__(128) flash_tc(
    const float* __restrict__ qs, const float* __restrict__ ks,
    const float* __restrict__ vs, float* __restrict__ out)
{
    extern __shared__ float sm[];
    float* Qs = sm;                     // [e][l] stride 136 (l = 0..127)
    float* Ks = Qs + 64 * 136;          // [e][s] stride 72
    float* Vs = Ks + 64 * 72;           // [s][e] stride 72
    float* Ps = Vs + 64 * 72;           // [l][s] stride 68 (l = 0..127)
    const int bh = blockIdx.y, b = bh >> 2, h = bh & 3;
    const int l0 = blockIdx.x * 128;
    const float* Q  = qs + ((size_t)b * DD + h * EE) * LL;
    const float* Kp = ks + ((size_t)b * DD + h * EE) * LL;
    const float* V  = vs + ((size_t)b * DD + h * EE) * LL;
    const int tid = threadIdx.x, wid = tid >> 5, lane = tid & 31;
    const int grp = lane >> 2, tig = lane & 3;
    const int lw = wid * 32;

    {
        int e = tid >> 1;
        int cb = (tid & 1) * 64;
#pragma unroll
        for (int w = 0; w < 16; w++) {
            int col = cb + w * 4;
            *(float4*)&Qs[e * 136 + col] = *(const float4*)&Q[(size_t)e * LL + l0 + col];
        }
    }

    float mI[2][2], li[2][2];
#pragma unroll
    for (int am = 0; am < 2; am++) {
        mI[am][0] = -1e30f; mI[am][1] = -1e30f;
        li[am][0] = 0.f; li[am][1] = 0.f;
    }
    float o[2][8][4];
#pragma unroll
    for (int am = 0; am < 2; am++)
#pragma unroll
        for (int en = 0; en < 8; en++)
#pragma unroll
            for (int q = 0; q < 4; q++) o[am][en][q] = 0.f;

    for (int s0 = 0; s0 < LL; s0 += 64) {
        __syncthreads();
        {
            int e = tid >> 1;
            int cb = (tid & 1) * 32;
#pragma unroll
            for (int w = 0; w < 8; w++) {
                int col = cb + w * 4;
                *(float4*)&Ks[e * 72 + col] = *(const float4*)&Kp[(size_t)e * LL + s0 + col];
                float4 vv = *(const float4*)&V[(size_t)e * LL + s0 + col];
                Vs[(col + 0) * 72 + e] = vv.x;
                Vs[(col + 1) * 72 + e] = vv.y;
                Vs[(col + 2) * 72 + e] = vv.z;
                Vs[(col + 3) * 72 + e] = vv.w;
            }
        }
        __syncthreads();

        float sa[2][8][4];
#pragma unroll
        for (int am = 0; am < 2; am++)
#pragma unroll
            for (int an = 0; an < 8; an++)
#pragma unroll
                for (int q = 0; q < 4; q++) sa[am][an][q] = 0.f;
#pragma unroll
        for (int k8 = 0; k8 < 64; k8 += 8) {
            uint32_t a[2][4];
#pragma unroll
            for (int am = 0; am < 2; am++) {
                int c = lw + am * 16 + grp;
                a[am][0] = f2tf(Qs[(k8 + tig) * 136 + c]);
                a[am][1] = f2tf(Qs[(k8 + tig) * 136 + c + 8]);
                a[am][2] = f2tf(Qs[(k8 + tig + 4) * 136 + c]);
                a[am][3] = f2tf(Qs[(k8 + tig + 4) * 136 + c + 8]);
            }
#pragma unroll
            for (int an = 0; an < 8; an++) {
                uint32_t bb[2];
                bb[0] = f2tf(Ks[(k8 + tig) * 72 + an * 8 + grp]);
                bb[1] = f2tf(Ks[(k8 + tig + 4) * 72 + an * 8 + grp]);
                mma_tf32(sa[0][an], a[0], bb);
                mma_tf32(sa[1][an], a[1], bb);
            }
        }

#pragma unroll
        for (int am = 0; am < 2; am++) {
            float mx0 = -1e30f, mx1 = -1e30f;
#pragma unroll
            for (int an = 0; an < 8; an++) {
#pragma unroll
                for (int q = 0; q < 4; q++) sa[am][an][q] *= 0.125f;
                mx0 = fmaxf(mx0, fmaxf(sa[am][an][0], sa[am][an][1]));
                mx1 = fmaxf(mx1, fmaxf(sa[am][an][2], sa[am][an][3]));
            }
            mx0 = fmaxf(mx0, __shfl_xor_sync(0xffffffffu, mx0, 1));
            mx0 = fmaxf(mx0, __shfl_xor_sync(0xffffffffu, mx0, 2));
            mx1 = fmaxf(mx1, __shfl_xor_sync(0xffffffffu, mx1, 1));
            mx1 = fmaxf(mx1, __shfl_xor_sync(0xffffffffu, mx1, 2));
            float mn0 = fmaxf(mI[am][0], mx0), mn1 = fmaxf(mI[am][1], mx1);
            float al0 = fexp(mI[am][0] - mn0), al1 = fexp(mI[am][1] - mn1);
            mI[am][0] = mn0; mI[am][1] = mn1;
            float ps0 = 0.f, ps1 = 0.f;
            int r = lw + am * 16 + grp;
#pragma unroll
            for (int an = 0; an < 8; an++) {
                float p0 = fexp(sa[am][an][0] - mn0);
                float p1 = fexp(sa[am][an][1] - mn0);
                float p2 = fexp(sa[am][an][2] - mn1);
                float p3 = fexp(sa[am][an][3] - mn1);
                ps0 += p0 + p1; ps1 += p2 + p3;
                float2 w0; w0.x = p0; w0.y = p1;
                float2 w1; w1.x = p2; w1.y = p3;
                *(float2*)&Ps[r * 68 + an * 8 + 2 * tig] = w0;
                *(float2*)&Ps[(r + 8) * 68 + an * 8 + 2 * tig] = w1;
            }
            ps0 += __shfl_xor_sync(0xffffffffu, ps0, 1);
            ps0 += __shfl_xor_sync(0xffffffffu, ps0, 2);
            ps1 += __shfl_xor_sync(0xffffffffu, ps1, 1);
            ps1 += __shfl_xor_sync(0xffffffffu, ps1, 2);
            li[am][0] = li[am][0] * al0 + ps0;
            li[am][1] = li[am][1] * al1 + ps1;
#pragma unroll
            for (int en = 0; en < 8; en++) {
                o[am][en][0] *= al0; o[am][en][1] *= al0;
                o[am][en][2] *= al1; o[am][en][3] *= al1;
            }
        }
        __syncwarp();

#pragma unroll
        for (int s8 = 0; s8 < 64; s8 += 8) {
            uint32_t a[2][4];
#pragma unroll
            for (int am = 0; am < 2; am++) {
                int r = lw + am * 16 + grp;
                a[am][0] = f2tf(Ps[r * 68 + s8 + tig]);
                a[am][1] = f2tf(Ps[(r + 8) * 68 + s8 + tig]);
                a[am][2] = f2tf(Ps[r * 68 + s8 + tig + 4]);
                a[am][3] = f2tf(Ps[(r + 8) * 68 + s8 + tig + 4]);
            }
#pragma unroll
            for (int en = 0; en < 8; en++) {
                uint32_t bb[2];
                bb[0] = f2tf(Vs[(s8 + tig) * 72 + en * 8 + grp]);
                bb[1] = f2tf(Vs[(s8 + tig + 4) * 72 + en * 8 + grp]);
                mma_tf32(o[0][en], a[0], bb);
                mma_tf32(o[1][en], a[1], bb);
            }
        }
    }

#pragma unroll
    for (int am = 0; am < 2; am++) {
        float inv0 = 1.0f / li[am][0], inv1 = 1.0f / li[am][1];
        int r = lw + am * 16 + grp;
#pragma unroll
        for (int en = 0; en < 8; en++) {
            int col = h * EE + en * 8 + 2 * tig;
            float2 w0; w0.x = o[am][en][0] * inv0; w0.y = o[am][en][1] * inv0;
            float2 w1; w1.x = o[am][en][2] * inv1; w1.y = o[am][en][3] * inv1;
            *(float2*)&out[((size_t)b * LL + l0 + r) * DD + col] = w0;
            *(float2*)&out[((size_t)b * LL + l0 + r + 8) * DD + col] = w1;
        }
    }
}

// ---------------- time delay aggregation (B,D,L) ----------------
__global__ void timeagg_k(const float* __restrict__ Vt, const float* __restrict__ w,
                          const int* __restrict__ idx, float* __restrict__ agg)
{
    int bd = blockIdx.x;
    int b = bd >> 8;
    __shared__ float row[1024];
    __shared__ float ws[TOPK];
    __shared__ int   is[TOPK];
    int t = threadIdx.x;
    for (int l = t; l < 1024; l += 256) row[l] = Vt[(size_t)bd * 1024 + l];
    if (t < TOPK) { ws[t] = w[(size_t)b * 64 + t]; is[t] = idx[t]; }
    __syncthreads();
    for (int l = t; l < 1024; l += 256) {
        float a = 0.f;
#pragma unroll
        for (int k = 0; k < TOPK; k++) a = fmaf(ws[k], row[(l + is[k]) & 1023], a);
        agg[(size_t)bd * 1024 + l] = a;
    }
}

// ---------------- context = 0.9*agg^T + 0.1*ctx_sp ----------------
__global__ void mix_k(const float* __restrict__ agg, const float* __restrict__ csp,
                      float* __restrict__ ctx)
{
    __shared__ float tile[32][33];
    int b = blockIdx.z;
    int l0 = blockIdx.x * 32, d0 = blockIdx.y * 32;
    int x = threadIdx.x, y = threadIdx.y;
#pragma unroll
    for (int i = 0; i < 32; i += 8)
        tile[y + i][x] = agg[((size_t)b * DD + d0 + y + i) * LL + l0 + x];
    __syncthreads();
#pragma unroll
    for (int i = 0; i < 32; i += 8) {
        size_t o = ((size_t)b * LL + l0 + y + i) * DD + d0 + x;
        ctx[o] = 0.9f * tile[x][y + i] + 0.1f * csp[o];
    }
}

// ---------------- LayerNorm over D=256, warp per row ----------------
__global__ void __launch_bounds__(256) ln_k(
    const float* __restrict__ in, const float* __restrict__ g,
    const float* __restrict__ b, float* __restrict__ out)
{
    const int lane = threadIdx.x & 31;
    const size_t row = (size_t)blockIdx.x * 8 + (threadIdx.x >> 5);
    const float* p = in + row * DD;
    float4 v0 = *(const float4*)&p[lane * 8];
    float4 v1 = *(const float4*)&p[lane * 8 + 4];
    float s = v0.x + v0.y + v0.z + v0.w + v1.x + v1.y + v1.z + v1.w;
#pragma unroll
    for (int off = 16; off > 0; off >>= 1)
        s += __shfl_xor_sync(0xffffffffu, s, off);
    float m = s * (1.0f / 256.0f);
    float d0x = v0.x - m, d0y = v0.y - m, d0z = v0.z - m, d0w = v0.w - m;
    float d1x = v1.x - m, d1y = v1.y - m, d1z = v1.z - m, d1w = v1.w - m;
    float vv = d0x * d0x + d0y * d0y + d0z * d0z + d0w * d0w
             + d1x * d1x + d1y * d1y + d1z * d1z + d1w * d1w;
#pragma unroll
    for (int off = 16; off > 0; off >>= 1)
        vv += __shfl_xor_sync(0xffffffffu, vv, off);
    float inv = rsqrtf(vv * (1.0f / 256.0f) + 1e-8f);
    float4 g0 = *(const float4*)&g[lane * 8];
    float4 g1 = *(const float4*)&g[lane * 8 + 4];
    float4 b0 = *(const float4*)&b[lane * 8];
    float4 b1 = *(const float4*)&b[lane * 8 + 4];
    float4 o0, o1;
    o0.x = d0x * inv * g0.x + b0.x; o0.y = d0y * inv * g0.y + b0.y;
    o0.z = d0z * inv * g0.z + b0.z; o0.w = d0w * inv * g0.w + b0.w;
    o1.x = d1x * inv * g1.x + b1.x; o1.y = d1y * inv * g1.y + b1.y;
    o1.z = d1z * inv * g1.z + b1.z; o1.w = d1w * inv * g1.w + b1.w;
    *(float4*)&out[row * DD + lane * 8] = o0;
    *(float4*)&out[row * DD + lane * 8 + 4] = o1;
}

// ---------------- launch ----------------
extern "C" void kernel_launch(void* const* d_in, const int* in_sizes, int n_in,
                              void* d_out, int out_size)
{
    const float* x   = (const float*)d_in[0];
    const float* Wq  = (const float*)d_in[1];
    const float* bq  = (const float*)d_in[2];
    const float* Wk  = (const float*)d_in[3];
    const float* bk  = (const float*)d_in[4];
    const float* Wv  = (const float*)d_in[5];
    const float* bv  = (const float*)d_in[6];
    const float* Wd  = (const float*)d_in[7];
    const float* bd  = (const float*)d_in[8];
    const float* ln1g = (const float*)d_in[9];
    const float* ln1b = (const float*)d_in[10];
    const float* W1  = (const float*)d_in[11];
    const float* b1  = (const float*)d_in[12];
    const float* W2  = (const float*)d_in[13];
    const float* b2  = (const float*)d_in[14];
    const float* ln2g = (const float*)d_in[15];
    const float* ln2b = (const float*)d_in[16];
    float* out = (float*)d_out;

    float* scr = nullptr;
    int* idxp = nullptr;
    cudaGetSymbolAddress((void**)&scr, g_scr);
    cudaGetSymbolAddress((void**)&idxp, g_idx);

    float* bQ   = scr + O_Q;   float* bK  = scr + O_K;   float* bV  = scr + O_V;
    float* Kt   = scr + O_KT;  float* Vt  = scr + O_VT;  float* trb = scr + O_TR;
    float* spQ  = scr + O_SPQ; float* spK = scr + O_SPK; float* spV = scr + O_SPV;
    float* qsb  = scr + O_QS;  float* vsb = scr + O_VS;
    float* csp  = scr + O_CSP; float* agg = scr + O_AGG; float* ctx = scr + O_CTX;
    float* t1   = scr + O_T1;  float* hb  = scr + O_H;
    float* g1b  = scr + O_G1;  float* fb  = scr + O_F;
    float* mv   = scr + O_MV;  float* wts = scr + O_W;

    const int flash_smem = (64 * 136 + 2 * 64 * 72 + 128 * 68) * sizeof(float); // 106496
    cudaFuncSetAttribute(flash_tc, cudaFuncAttributeMaxDynamicSharedMemorySize, flash_smem);
    const int fft_smem = (768 + 8 * 1056) * sizeof(float2);                      // 73728
    cudaFuncSetAttribute(fftfwd_k, cudaFuncAttributeMaxDynamicSharedMemorySize, fft_smem);
    cudaFuncSetAttribute(fftinv_k, cudaFuncAttributeMaxDynamicSharedMemorySize, fft_smem);

    const dim3 tb(32, 8);

    // 1. QKV projections (tf32 tensor cores)
    gemm_tc<1><<<dim3(2, 256), 256>>>(x, Wq, bq, nullptr, bQ, BB * LL, DD, DD);
    gemm_tc<1><<<dim3(2, 256), 256>>>(x, Wk, bk, nullptr, bK, BB * LL, DD, DD);
    gemm_tc<1><<<dim3(2, 256), 256>>>(x, Wv, bv, nullptr, bV, BB * LL, DD, DD);

    // 2. fused transposes to (B,D,L): bK->Kt, bV->Vt, bQ->trb
    tr3_k<<<dim3(8, 32, 96), tb>>>(bK, bV, bQ, Kt, Vt, trb);

    // 3. forward band FFT (register radix-4, 8 rows/block)
    fftfwd_k<<<BB * DD / 8, 512, fft_smem>>>(trb, spQ);
    fftfwd_k<<<BB * DD / 8, 512, fft_smem>>>(Kt, spK);
    fftfwd_k<<<BB * DD / 8, 512, fft_smem>>>(Vt, spV);

    // 4. corr mean path (partials -> meanv folds reduction; topk folds weights)
    corr_part_k<<<dim3(8, BB), 256>>>(spQ, spK, t1);
    meanv_k<<<dim3(BB, 4), 256>>>(t1, mv);
    topk_k<<<1, 1024>>>(mv, idxp, wts);

    // 5. inverse band FFT -> qs, vs
    fftinv_k<<<BB * DD / 8, 512, fft_smem>>>(spQ, qsb);
    fftinv_k<<<BB * DD / 8, 512, fft_smem>>>(spV, vsb);

    // 6. spatial attention (tf32; K = raw Kt)
    flash_tc<<<dim3(8, BB * HH), 128, flash_smem>>>(qsb, Kt, vsb, csp);

    // 7. time aggregation + mix
    timeagg_k<<<BB * DD, 256>>>(Vt, wts, idxp, agg);
    mix_k<<<dim3(32, 8, BB), tb>>>(agg, csp, ctx);

    // 8. output projection + residual + LN1
    gemm_tc<2><<<dim3(2, 256), 256>>>(ctx, Wd, bd, x, t1, BB * LL, DD, DD);
    ln_k<<<BB * LL / 8, 256>>>(t1, ln1g, ln1b, hb);

    // 9. FFN + LN2
    gemm_tc<3><<<dim3(2, 256), 256>>>(hb, W1, b1, nullptr, g1b, BB * LL, DD, DD);
    gemm_tc<2><<<dim3(2, 256), 256>>>(g1b, W2, b2, hb, fb, BB * LL, DD, DD);
    ln_k<<<BB * LL / 8, 256>>>(fb, ln2g, ln2b, out);
}

// round 17
// speedup vs baseline: 1.0174x; 1.0174x over previous
#include <cuda_runtime.h>
#include <math.h>
#include <stdint.h>

// ---------------- problem constants ----------------
#define BB 32
#define LL 1024
#define DD 256
#define HH 4
#define EE 64
#define NBAND 308          // f = 205..512
#define F0 205
#define TOPK 34

// ---------------- scratch layout (floats) ----------------
constexpr size_t SZ   = (size_t)BB * LL * DD;        // 8388608
constexpr size_t SPEC = (size_t)BB * DD * 640;       // 5242880 (8192 x 640)

constexpr size_t O_Q    = 0;
constexpr size_t O_K    = O_Q + SZ;
constexpr size_t O_V    = O_K + SZ;
// FFT source order: KT, VT, TR(Q) contiguous
constexpr size_t O_KT   = O_V + SZ;
constexpr size_t O_VT   = O_KT + SZ;
constexpr size_t O_TR   = O_VT + SZ;       // Qt
// FFT dest order matches: SPK, SPV, SPQ contiguous; inverse uses SPV,SPQ adjacent
constexpr size_t O_SPK  = O_TR + SZ;
constexpr size_t O_SPV  = O_SPK + SPEC;
constexpr size_t O_SPQ  = O_SPV + SPEC;
// inverse dests: VS, QS contiguous (match SPV,SPQ order)
constexpr size_t O_VS   = O_SPQ + SPEC;
constexpr size_t O_QS   = O_VS + SZ;
constexpr size_t O_CSP  = O_QS + SZ;       // ctx spatial (B,L,D)
constexpr size_t O_AGG  = O_CSP + SZ;      // time agg (B,D,L)
constexpr size_t O_CTX  = O_AGG + SZ;      // mixed context (B,L,D)
constexpr size_t O_T1   = O_CTX + SZ;      // also corr partials scratch
constexpr size_t O_H    = O_T1 + SZ;
constexpr size_t O_G1   = O_H + SZ;
constexpr size_t O_F    = O_G1 + SZ;
constexpr size_t O_MV   = O_F + SZ;                 // mean_value 32x1024
constexpr size_t O_W    = O_MV + (size_t)BB * LL;   // weights 32x64
constexpr size_t TOTAL  = O_W + (size_t)BB * 64;

__device__ float g_scr[TOTAL + 1024];
__device__ int   g_idx[64];

// ---------------- cp.async helpers ----------------
__device__ __forceinline__ void cpa16(uint32_t saddr, const void* gptr) {
    asm volatile("cp.async.cg.shared.global [%0], [%1], 16;" :: "r"(saddr), "l"(gptr));
}
__device__ __forceinline__ void cpa_commit() {
    asm volatile("cp.async.commit_group;");
}
template<int N>
__device__ __forceinline__ void cpa_wait() {
    asm volatile("cp.async.wait_group %0;" :: "n"(N));
}

// ---------------- tf32 mma helpers ----------------
__device__ __forceinline__ uint32_t f2tf(float f) {
    return __float_as_uint(f);   // hardware tf32 mma truncates to top 19 bits
}
__device__ __forceinline__ void mma_tf32(float* d, const uint32_t* a, const uint32_t* b) {
    asm volatile(
        "mma.sync.aligned.m16n8k8.row.col.f32.tf32.tf32.f32 "
        "{%0,%1,%2,%3}, {%4,%5,%6,%7}, {%8,%9}, {%0,%1,%2,%3};"
        : "+f"(d[0]), "+f"(d[1]), "+f"(d[2]), "+f"(d[3])
        : "r"(a[0]), "r"(a[1]), "r"(a[2]), "r"(a[3]), "r"(b[0]), "r"(b[1]));
}

// ---------------- fast exp on the FMA pipe ----------------
__device__ __forceinline__ float fexp(float x) {
    x = fmaxf(x, -87.0f);
    float z = x * 1.4426950408889634f;
    float r = rintf(z);
    float f = z - r;
    float p = 1.5403530e-4f;
    p = fmaf(p, f, 1.3333558e-3f);
    p = fmaf(p, f, 9.6181291e-3f);
    p = fmaf(p, f, 5.5504109e-2f);
    p = fmaf(p, f, 2.4022651e-1f);
    p = fmaf(p, f, 6.9314718e-1f);
    p = fmaf(p, f, 1.0f);
    int e = (int)r;
    return __int_as_float((e + 127) << 23) * p;
}

// ---------------- 1024-pt radix-4 FFT, register-resident ----------------
__device__ __forceinline__ int rev4_10(int l) {
    int b = __brev((unsigned)l) >> 22;
    return ((b & 0x155) << 1) | ((b & 0x2AA) >> 1);
}
__device__ __forceinline__ float2 cmul(float2 a, float2 b) {
    return make_float2(a.x * b.x - a.y * b.y, a.x * b.y + a.y * b.x);
}
__device__ __forceinline__ int IDX(int p) { return p + (p >> 5); }   // skew

template<bool INV>
__device__ __forceinline__ void bf4(float2& A, float2& B, float2& C, float2& D,
                                    float2 w1, float2 w2, float2 w3)
{
    float2 b = cmul(B, w1), c = cmul(C, w2), d = cmul(D, w3);
    float2 t0 = make_float2(A.x + c.x, A.y + c.y);
    float2 t1 = make_float2(A.x - c.x, A.y - c.y);
    float2 t2 = make_float2(b.x + d.x, b.y + d.y);
    float2 t3 = make_float2(b.x - d.x, b.y - d.y);
    A = make_float2(t0.x + t2.x, t0.y + t2.y);
    C = make_float2(t0.x - t2.x, t0.y - t2.y);
    if (!INV) {
        B = make_float2(t1.x + t3.y, t1.y - t3.x);
        D = make_float2(t1.x - t3.y, t1.y + t3.x);
    } else {
        B = make_float2(t1.x - t3.y, t1.y + t3.x);
        D = make_float2(t1.x + t3.y, t1.y - t3.x);
    }
}

template<bool INV>
__device__ __forceinline__ void fft_reg(float2* sb, const float2* tw, int th,
                                        float2 (&r)[16])
{
    // phase A: 16 consecutive elements; stages 0 (unit twiddles) and 1
#pragma unroll
    for (int i = 0; i < 16; i++) r[i] = sb[IDX(th * 16 + i)];
    const float2 one = make_float2(1.f, 0.f);
#pragma unroll
    for (int a = 0; a < 4; a++)
        bf4<INV>(r[4*a], r[4*a+1], r[4*a+2], r[4*a+3], one, one, one);
#pragma unroll
    for (int pos = 0; pos < 4; pos++) {
        int e = pos << 6;
        bf4<INV>(r[pos], r[pos+4], r[pos+8], r[pos+12], tw[e], tw[2*e], tw[3*e]);
    }
#pragma unroll
    for (int i = 0; i < 16; i++) sb[IDX(th * 16 + i)] = r[i];
    __syncthreads();

    // phase B: ownership p = 256c + 16m + rb; stages 2 and 3
    const int c = th >> 4, rb = th & 15;
    const int pb = 256 * c + rb;
#pragma unroll
    for (int m = 0; m < 16; m++) r[m] = sb[IDX(pb + 16 * m)];
    {
        int e = rb << 4;
        float2 w1 = tw[e], w2 = tw[2*e], w3 = tw[3*e];
#pragma unroll
        for (int a = 0; a < 4; a++)
            bf4<INV>(r[4*a], r[4*a+1], r[4*a+2], r[4*a+3], w1, w2, w3);
    }
#pragma unroll
    for (int m0 = 0; m0 < 4; m0++) {
        int e = 64 * m0 + 4 * rb;
        bf4<INV>(r[m0], r[m0+4], r[m0+8], r[m0+12], tw[e], tw[2*e], tw[3*e]);
    }
#pragma unroll
    for (int m = 0; m < 16; m++) sb[IDX(pb + 16 * m)] = r[m];
    __syncthreads();

    // phase C: ownership q = 4*th + i, elements q + 256k; stage 4
#pragma unroll
    for (int i = 0; i < 4; i++)
#pragma unroll
        for (int k = 0; k < 4; k++)
            r[4*i + k] = sb[IDX(4*th + i + 256*k)];
#pragma unroll
    for (int i = 0; i < 4; i++) {
        int e = 4*th + i;
        bf4<INV>(r[4*i], r[4*i+1], r[4*i+2], r[4*i+3], tw[e], tw[2*e], tw[3*e]);
    }
}

// Forward FFT: 8 rows per block, 512 threads (64/row), dynamic smem.
// Grid covers 3*BB*DD rows (KT|VT|TR contiguous -> SPK|SPV|SPQ contiguous).
__global__ void __launch_bounds__(512) fftfwd_k(
    const float* __restrict__ in, float* __restrict__ spec)
{
    extern __shared__ float2 fsm[];
    float2* tw = fsm;               // 768
    float2* s  = fsm + 768;         // 8 * 1056
    const int th = threadIdx.x & 63;
    const int rr = threadIdx.x >> 6;
    const int row = blockIdx.x * 8 + rr;
    const float* xr = in + (size_t)row * LL;
    float2* sb = s + rr * 1056;

    for (int k = threadIdx.x; k < 768; k += 512) {
        float ang = -6.283185307179586f * (float)k / 1024.0f;
        tw[k] = make_float2(cosf(ang), sinf(ang));
    }
    for (int l = th; l < 1024; l += 64)
        sb[IDX(rev4_10(l))] = make_float2(xr[l], 0.f);
    __syncthreads();

    float2 r[16];
    fft_reg<false>(sb, tw, th, r);

#pragma unroll
    for (int i = 0; i < 4; i++)
#pragma unroll
        for (int k = 0; k < 4; k++) {
            int idx = 4*th + i + 256*k;
            if (idx >= F0 && idx <= 512) {
                spec[(size_t)row * 640 + idx - F0]       = r[4*i + k].x;
                spec[(size_t)row * 640 + 320 + idx - F0] = r[4*i + k].y;
            }
        }
}

// Inverse FFT: 8 rows per block. Grid covers 2*BB*DD rows (SPV|SPQ -> VS|QS).
__global__ void __launch_bounds__(512) fftinv_k(
    const float* __restrict__ spec, float* __restrict__ outr)
{
    extern __shared__ float2 fsm[];
    float2* tw = fsm;
    float2* s  = fsm + 768;
    const int th = threadIdx.x & 63;
    const int rr = threadIdx.x >> 6;
    const int row = blockIdx.x * 8 + rr;
    const float* sp = spec + (size_t)row * 640;
    float2* sb = s + rr * 1056;

    for (int k = threadIdx.x; k < 768; k += 512) {
        float ang = 6.283185307179586f * (float)k / 1024.0f;
        tw[k] = make_float2(cosf(ang), sinf(ang));
    }
    for (int l = th; l < 1024; l += 64) {
        float2 v = make_float2(0.f, 0.f);
        if (l >= F0 && l <= 512) {
            v.x = sp[l - F0];
            v.y = sp[320 + l - F0];
        } else if (l >= 513 && l <= 1024 - F0) {
            int f = 1024 - l;
            v.x = sp[f - F0];
            v.y = -sp[320 + f - F0];
        }
        sb[IDX(rev4_10(l))] = v;
    }
    __syncthreads();

    float2 r[16];
    fft_reg<true>(sb, tw, th, r);

    const float sc = 1.0f / 1024.0f;
#pragma unroll
    for (int k = 0; k < 4; k++) {
        float4 o;
        o.x = r[0 + k].x * sc;
        o.y = r[4 + k].x * sc;
        o.z = r[8 + k].x * sc;
        o.w = r[12 + k].x * sc;
        *(float4*)&outr[(size_t)row * LL + 4*th + 256*k] = o;
    }
}

// ---------------- tf32 GEMM core (128x128 block), shared by variants ------
struct GemmSmem {
    float As[2][128][20];
    float Bs[2][16][136];
};

template<int EPI>
__device__ __forceinline__ void gemm_core(
    GemmSmem* smp,
    const float* __restrict__ A, const float* __restrict__ Bw,
    const float* __restrict__ bias, const float* __restrict__ res,
    float* __restrict__ C, int M, int N, int K, int bn, int bm)
{
    float (*As)[128][20] = smp->As;
    float (*Bs)[16][136] = smp->Bs;
    const int tid = threadIdx.x, wid = tid >> 5, lane = tid & 31;
    const int grp = lane >> 2, tig = lane & 3;
    const int wm = (wid & 3) * 32, wn = (wid >> 2) * 64;

    const uint32_t asb = (uint32_t)__cvta_generic_to_shared(&As[0][0][0]);
    const uint32_t bsb = (uint32_t)__cvta_generic_to_shared(&Bs[0][0][0]);
    const int T = K >> 4;

    auto loadA = [&](int st, int k0) {
#pragma unroll
        for (int u = 0; u < 2; u++) {
            int c = tid + u * 256;
            int row = c >> 2, kq = (c & 3) * 4;
            cpa16(asb + (uint32_t)(st * 128 * 20 + row * 20 + kq) * 4,
                  &A[(size_t)(bm + row) * K + k0 + kq]);
        }
    };
    auto loadB = [&](int st, int k0) {
#pragma unroll
        for (int u = 0; u < 2; u++) {
            int c = tid + u * 256;
            int r = c >> 5, col = (c & 31) * 4;
            cpa16(bsb + (uint32_t)(st * 16 * 136 + r * 136 + col) * 4,
                  &Bw[(size_t)(k0 + r) * N + bn + col]);
        }
    };

    loadA(0, 0); loadB(0, 0); cpa_commit();

    float d[2][8][4];
#pragma unroll
    for (int am = 0; am < 2; am++)
#pragma unroll
        for (int an = 0; an < 8; an++)
#pragma unroll
            for (int q = 0; q < 4; q++) d[am][an][q] = 0.f;

    for (int kt = 0; kt < T; kt++) {
        if (kt + 1 < T) {
            loadA((kt + 1) & 1, (kt + 1) << 4);
            loadB((kt + 1) & 1, (kt + 1) << 4);
            cpa_commit();
            cpa_wait<1>();
        } else {
            cpa_wait<0>();
        }
        __syncthreads();
        const int st = kt & 1;
#pragma unroll
        for (int k8 = 0; k8 < 16; k8 += 8) {
            uint32_t a[2][4];
#pragma unroll
            for (int am = 0; am < 2; am++) {
                int mr = wm + am * 16;
                a[am][0] = f2tf(As[st][mr + grp][k8 + tig]);
                a[am][1] = f2tf(As[st][mr + grp + 8][k8 + tig]);
                a[am][2] = f2tf(As[st][mr + grp][k8 + tig + 4]);
                a[am][3] = f2tf(As[st][mr + grp + 8][k8 + tig + 4]);
            }
#pragma unroll
            for (int an = 0; an < 8; an++) {
                uint32_t b[2];
                b[0] = f2tf(Bs[st][k8 + tig][wn + an * 8 + grp]);
                b[1] = f2tf(Bs[st][k8 + tig + 4][wn + an * 8 + grp]);
                mma_tf32(d[0][an], a[0], b);
                mma_tf32(d[1][an], a[1], b);
            }
        }
        __syncthreads();
    }

#pragma unroll
    for (int am = 0; am < 2; am++) {
        int row0 = bm + wm + am * 16 + grp;
#pragma unroll
        for (int an = 0; an < 8; an++) {
            int col = bn + wn + an * 8 + 2 * tig;
            float o0 = d[am][an][0], o1 = d[am][an][1];
            float o2 = d[am][an][2], o3 = d[am][an][3];
            float2 bv = *(const float2*)&bias[col];
            o0 += bv.x; o1 += bv.y; o2 += bv.x; o3 += bv.y;
            if (EPI == 2) {
                float2 r0v = *(const float2*)&res[(size_t)row0 * N + col];
                float2 r1v = *(const float2*)&res[(size_t)(row0 + 8) * N + col];
                o0 += r0v.x; o1 += r0v.y; o2 += r1v.x; o3 += r1v.y;
            }
            if (EPI == 3) {
                o0 = o0 * 0.5f * (1.0f + erff(o0 * 0.70710678118654752f));
                o1 = o1 * 0.5f * (1.0f + erff(o1 * 0.70710678118654752f));
                o2 = o2 * 0.5f * (1.0f + erff(o2 * 0.70710678118654752f));
                o3 = o3 * 0.5f * (1.0f + erff(o3 * 0.70710678118654752f));
            }
            float2 w0; w0.x = o0; w0.y = o1;
            float2 w1; w1.x = o2; w1.y = o3;
            *(float2*)&C[(size_t)row0 * N + col] = w0;
            *(float2*)&C[(size_t)(row0 + 8) * N + col] = w1;
        }
    }
}

template<int EPI>
__global__ void __launch_bounds__(256) gemm_tc(
    const float* __restrict__ A, const float* __restrict__ Bw,
    const float* __restrict__ bias, const float* __restrict__ res,
    float* __restrict__ C, int M, int N, int K)
{
    __shared__ GemmSmem smp;
    gemm_core<EPI>(&smp, A, Bw, bias, res, C, M, N, K,
                   blockIdx.x * 128, blockIdx.y * 128);
}

// QKV fused: grid.z = 0/1/2 selects (Wq,bq,bQ) / (Wk,bk,bK) / (Wv,bv,bV)
__global__ void __launch_bounds__(256) gemm_qkv(
    const float* __restrict__ A,
    const float* __restrict__ Wq, const float* __restrict__ bq, float* __restrict__ Cq,
    const float* __restrict__ Wk, const float* __restrict__ bk, float* __restrict__ Ck,
    const float* __restrict__ Wv, const float* __restrict__ bv, float* __restrict__ Cv)
{
    __shared__ GemmSmem smp;
    int z = blockIdx.z;
    const float* Bw = (z == 0) ? Wq : (z == 1) ? Wk : Wv;
    const float* bias = (z == 0) ? bq : (z == 1) ? bk : bv;
    float* C = (z == 0) ? Cq : (z == 1) ? Ck : Cv;
    gemm_core<1>(&smp, A, Bw, bias, nullptr, C, BB * LL, DD, DD,
                 blockIdx.x * 128, blockIdx.y * 128);
}

// ---------------- fused triple transpose: (B,L,D) -> (B,D,L) x3 ----------
__global__ void tr3_k(const float* __restrict__ sK, const float* __restrict__ sV,
                      const float* __restrict__ sQ,
                      float* __restrict__ dK, float* __restrict__ dV,
                      float* __restrict__ dQ)
{
    __shared__ float tile[32][33];
    int z = blockIdx.z;
    int tsr = z >> 5, b = z & 31;
    const float* I = (tsr == 0 ? sK : tsr == 1 ? sV : sQ) + (size_t)b * LL * DD;
    float* O = (tsr == 0 ? dK : tsr == 1 ? dV : dQ) + (size_t)b * LL * DD;
    int c0 = blockIdx.x * 32, r0 = blockIdx.y * 32;
    int x = threadIdx.x, y = threadIdx.y;
#pragma unroll
    for (int i = 0; i < 32; i += 8)
        tile[y + i][x] = I[(size_t)(r0 + y + i) * DD + c0 + x];
    __syncthreads();
#pragma unroll
    for (int i = 0; i < 32; i += 8)
        O[(size_t)(c0 + y + i) * LL + r0 + x] = tile[x][y + i];
}

// ---------------- corr spectrum sum, pass 1 ----------
__global__ void __launch_bounds__(256) corr_part_k(
    const float* __restrict__ Qs, const float* __restrict__ Ks,
    float* __restrict__ Spart)
{
    const int g = blockIdx.x, b = blockIdx.y;
    const int t = threadIdx.x;
    const int j0 = t, j1 = t + 256;
    float re0 = 0.f, im0 = 0.f, re1 = 0.f, im1 = 0.f;
    size_t base = ((size_t)(b * 256 + g * 32)) * 640;
    for (int r = 0; r < 32; r++) {
        size_t row = base + (size_t)r * 640;
        float qr = Qs[row + j0], qi = Qs[row + 320 + j0];
        float kr = Ks[row + j0], ki = Ks[row + 320 + j0];
        re0 += qr * kr + qi * ki;
        im0 += qi * kr - qr * ki;
        if (j1 < NBAND) {
            qr = Qs[row + j1]; qi = Qs[row + 320 + j1];
            kr = Ks[row + j1]; ki = Ks[row + 320 + j1];
            re1 += qr * kr + qi * ki;
            im1 += qi * kr - qr * ki;
        }
    }
    size_t o = (size_t)(b * 8 + g) * 640;
    Spart[o + j0] = re0;
    Spart[o + 320 + j0] = im0;
    if (j1 < NBAND) {
        Spart[o + j1] = re1;
        Spart[o + 320 + j1] = im1;
    } else if (j1 < 320) {
        Spart[o + j1] = 0.f;
        Spart[o + 320 + j1] = 0.f;
    }
}

// ---------------- mean_value (folds 8-partial reduction in) ----------------
__global__ void __launch_bounds__(256) meanv_k(
    const float* __restrict__ Spart, float* __restrict__ mv)
{
    int b = blockIdx.x, t = threadIdx.x;
    __shared__ float sre[NBAND], sim[NBAND], tbl[1024];
    for (int j = t; j < NBAND; j += 256) {
        float ar = 0.f, ai = 0.f;
#pragma unroll
        for (int g = 0; g < 8; g++) {
            size_t o = (size_t)(b * 8 + g) * 640;
            ar += Spart[o + j];
            ai += Spart[o + 320 + j];
        }
        sre[j] = ar;
        sim[j] = ai;
    }
    for (int m = t; m < 1024; m += 256)
        tbl[m] = cosf(6.283185307179586f * (float)m / 1024.0f);
    __syncthreads();
    int tt = blockIdx.y * 256 + t;
    float acc = sre[NBAND - 1] * ((tt & 1) ? -1.f : 1.f);
    for (int j = 0; j < NBAND - 1; j++) {
        int f = F0 + j;
        int m = (f * tt) & 1023;
        float c = tbl[m];
        float s = tbl[(m + 768) & 1023];
        acc += 2.f * (sre[j] * c - sim[j] * s);
    }
    mv[(size_t)b * 1024 + tt] = acc * (1.0f / (256.0f * 1024.0f));
}

// ---------------- top-k over batch-mean + per-batch softmax weights --------
__global__ void topk_k(const float* __restrict__ mv, int* __restrict__ idxout,
                       float* __restrict__ w)
{
    int t = threadIdx.x;  // 1024
    __shared__ float vals[1024];
    __shared__ float rv[1024];
    __shared__ int   ri[1024];
    __shared__ int   is[TOPK];
    float g = 0.f;
    for (int b = 0; b < BB; b++) g += mv[(size_t)b * 1024 + t];
    vals[t] = g;
    __syncthreads();
    for (int k = 0; k < TOPK; k++) {
        rv[t] = vals[t]; ri[t] = t; __syncthreads();
        for (int s = 512; s > 0; s >>= 1) {
            if (t < s) {
                if (rv[t + s] > rv[t] || (rv[t + s] == rv[t] && ri[t + s] < ri[t])) {
                    rv[t] = rv[t + s]; ri[t] = ri[t + s];
                }
            }
            __syncthreads();
        }
        if (t == 0) { idxout[k] = ri[0]; is[k] = ri[0]; vals[ri[0]] = -3.4e38f; }
        __syncthreads();
    }
    int b = t >> 5, lane = t & 31;
    float v0 = mv[(size_t)b * 1024 + is[lane < TOPK ? lane : 0]];
    if (lane >= TOPK) v0 = -3.4e38f;
    float v1 = (lane + 32 < TOPK) ? mv[(size_t)b * 1024 + is[lane + 32]] : -3.4e38f;
    float mx = fmaxf(v0, v1);
#pragma unroll
    for (int off = 16; off > 0; off >>= 1)
        mx = fmaxf(mx, __shfl_xor_sync(0xffffffffu, mx, off));
    float e0 = (lane < TOPK) ? expf(v0 - mx) : 0.f;
    float e1 = (lane + 32 < TOPK) ? expf(v1 - mx) : 0.f;
    float sm = e0 + e1;
#pragma unroll
    for (int off = 16; off > 0; off >>= 1)
        sm += __shfl_xor_sync(0xffffffffu, sm, off);
    float inv = 1.0f / sm;
    if (lane < TOPK) w[(size_t)b * 64 + lane] = e0 * inv;
    if (lane + 32 < TOPK) w[(size_t)b * 64 + lane + 32] = e1 * inv;
}

// ---------------- flash attention, tf32 tensor cores, 2 m-atoms/warp -------
__global__ void __launch_bounds__(128) flash_tc(
    const float* __restrict__ qs, const float* __restrict__ ks,
    const float* __restrict__ vs, float* __restrict__ out)
{
    extern __shared__ float sm[];
    float* Qs = sm;                     // [e][l] stride 136 (l = 0..127)
    float* Ks = Qs + 64 * 136;          // [e][s] stride 72
    float* Vs = Ks + 64 * 72;           // [s][e] stride 72
    float* Ps = Vs + 64 * 72;           // [l][s] stride 68 (l = 0..127)
    const int bh = blockIdx.y, b = bh >> 2, h = bh & 3;
    const int l0 = blockIdx.x * 128;
    const float* Q  = qs + ((size_t)b * DD + h * EE) * LL;
    const float* Kp = ks + ((size_t)b * DD + h * EE) * LL;
    const float* V  = vs + ((size_t)b * DD + h * EE) * LL;
    const int tid = threadIdx.x, wid = tid >> 5, lane = tid & 31;
    const int grp = lane >> 2, tig = lane & 3;
    const int lw = wid * 32;

    {
        int e = tid >> 1;
        int cb = (tid & 1) * 64;
#pragma unroll
        for (int w = 0; w < 16; w++) {
            int col = cb + w * 4;
            *(float4*)&Qs[e * 136 + col] = *(const float4*)&Q[(size_t)e * LL + l0 + col];
        }
    }

    float mI[2][2], li[2][2];
#pragma unroll
    for (int am = 0; am < 2; am++) {
        mI[am][0] = -1e30f; mI[am][1] = -1e30f;
        li[am][0] = 0.f; li[am][1] = 0.f;
    }
    float o[2][8][4];
#pragma unroll
    for (int am = 0; am < 2; am++)
#pragma unroll
        for (int en = 0; en < 8; en++)
#pragma unroll
            for (int q = 0; q < 4; q++) o[am][en][q] = 0.f;

    for (int s0 = 0; s0 < LL; s0 += 64) {
        __syncthreads();
        {
            int e = tid >> 1;
            int cb = (tid & 1) * 32;
#pragma unroll
            for (int w = 0; w < 8; w++) {
                int col = cb + w * 4;
                *(float4*)&Ks[e * 72 + col] = *(const float4*)&Kp[(size_t)e * LL + s0 + col];
                float4 vv = *(const float4*)&V[(size_t)e * LL + s0 + col];
                Vs[(col + 0) * 72 + e] = vv.x;
                Vs[(col + 1) * 72 + e] = vv.y;
                Vs[(col + 2) * 72 + e] = vv.z;
                Vs[(col + 3) * 72 + e] = vv.w;
            }
        }
        __syncthreads();

        float sa[2][8][4];
#pragma unroll
        for (int am = 0; am < 2; am++)
#pragma unroll
            for (int an = 0; an < 8; an++)
#pragma unroll
                for (int q = 0; q < 4; q++) sa[am][an][q] = 0.f;
#pragma unroll
        for (int k8 = 0; k8 < 64; k8 += 8) {
            uint32_t a[2][4];
#pragma unroll
            for (int am = 0; am < 2; am++) {
                int c = lw + am * 16 + grp;
                a[am][0] = f2tf(Qs[(k8 + tig) * 136 + c]);
                a[am][1] = f2tf(Qs[(k8 + tig) * 136 + c + 8]);
                a[am][2] = f2tf(Qs[(k8 + tig + 4) * 136 + c]);
                a[am][3] = f2tf(Qs[(k8 + tig + 4) * 136 + c + 8]);
            }
#pragma unroll
            for (int an = 0; an < 8; an++) {
                uint32_t bb[2];
                bb[0] = f2tf(Ks[(k8 + tig) * 72 + an * 8 + grp]);
                bb[1] = f2tf(Ks[(k8 + tig + 4) * 72 + an * 8 + grp]);
                mma_tf32(sa[0][an], a[0], bb);
                mma_tf32(sa[1][an], a[1], bb);
            }
        }

#pragma unroll
        for (int am = 0; am < 2; am++) {
            float mx0 = -1e30f, mx1 = -1e30f;
#pragma unroll
            for (int an = 0; an < 8; an++) {
#pragma unroll
                for (int q = 0; q < 4; q++) sa[am][an][q] *= 0.125f;
                mx0 = fmaxf(mx0, fmaxf(sa[am][an][0], sa[am][an][1]));
                mx1 = fmaxf(mx1, fmaxf(sa[am][an][2], sa[am][an][3]));
            }
            mx0 = fmaxf(mx0, __shfl_xor_sync(0xffffffffu, mx0, 1));
            mx0 = fmaxf(mx0, __shfl_xor_sync(0xffffffffu, mx0, 2));
            mx1 = fmaxf(mx1, __shfl_xor_sync(0xffffffffu, mx1, 1));
            mx1 = fmaxf(mx1, __shfl_xor_sync(0xffffffffu, mx1, 2));
            float mn0 = fmaxf(mI[am][0], mx0), mn1 = fmaxf(mI[am][1], mx1);
            float al0 = fexp(mI[am][0] - mn0), al1 = fexp(mI[am][1] - mn1);
            mI[am][0] = mn0; mI[am][1] = mn1;
            float ps0 = 0.f, ps1 = 0.f;
            int r = lw + am * 16 + grp;
#pragma unroll
            for (int an = 0; an < 8; an++) {
                float p0 = fexp(sa[am][an][0] - mn0);
                float p1 = fexp(sa[am][an][1] - mn0);
                float p2 = fexp(sa[am][an][2] - mn1);
                float p3 = fexp(sa[am][an][3] - mn1);
                ps0 += p0 + p1; ps1 += p2 + p3;
                float2 w0; w0.x = p0; w0.y = p1;
                float2 w1; w1.x = p2; w1.y = p3;
                *(float2*)&Ps[r * 68 + an * 8 + 2 * tig] = w0;
                *(float2*)&Ps[(r + 8) * 68 + an * 8 + 2 * tig] = w1;
            }
            ps0 += __shfl_xor_sync(0xffffffffu, ps0, 1);
            ps0 += __shfl_xor_sync(0xffffffffu, ps0, 2);
            ps1 += __shfl_xor_sync(0xffffffffu, ps1, 1);
            ps1 += __shfl_xor_sync(0xffffffffu, ps1, 2);
            li[am][0] = li[am][0] * al0 + ps0;
            li[am][1] = li[am][1] * al1 + ps1;
#pragma unroll
            for (int en = 0; en < 8; en++) {
                o[am][en][0] *= al0; o[am][en][1] *= al0;
                o[am][en][2] *= al1; o[am][en][3] *= al1;
            }
        }
        __syncwarp();

#pragma unroll
        for (int s8 = 0; s8 < 64; s8 += 8) {
            uint32_t a[2][4];
#pragma unroll
            for (int am = 0; am < 2; am++) {
                int r = lw + am * 16 + grp;
                a[am][0] = f2tf(Ps[r * 68 + s8 + tig]);
                a[am][1] = f2tf(Ps[(r + 8) * 68 + s8 + tig]);
                a[am][2] = f2tf(Ps[r * 68 + s8 + tig + 4]);
                a[am][3] = f2tf(Ps[(r + 8) * 68 + s8 + tig + 4]);
            }
#pragma unroll
            for (int en = 0; en < 8; en++) {
                uint32_t bb[2];
                bb[0] = f2tf(Vs[(s8 + tig) * 72 + en * 8 + grp]);
                bb[1] = f2tf(Vs[(s8 + tig + 4) * 72 + en * 8 + grp]);
                mma_tf32(o[0][en], a[0], bb);
                mma_tf32(o[1][en], a[1], bb);
            }
        }
    }

#pragma unroll
    for (int am = 0; am < 2; am++) {
        float inv0 = 1.0f / li[am][0], inv1 = 1.0f / li[am][1];
        int r = lw + am * 16 + grp;
#pragma unroll
        for (int en = 0; en < 8; en++) {
            int col = h * EE + en * 8 + 2 * tig;
            float2 w0; w0.x = o[am][en][0] * inv0; w0.y = o[am][en][1] * inv0;
            float2 w1; w1.x = o[am][en][2] * inv1; w1.y = o[am][en][3] * inv1;
            *(float2*)&out[((size_t)b * LL + l0 + r) * DD + col] = w0;
            *(float2*)&out[((size_t)b * LL + l0 + r + 8) * DD + col] = w1;
        }
    }
}

// ---------------- time delay aggregation (B,D,L) ----------------
__global__ void timeagg_k(const float* __restrict__ Vt, const float* __restrict__ w,
                          const int* __restrict__ idx, float* __restrict__ agg)
{
    int bd = blockIdx.x;
    int b = bd >> 8;
    __shared__ float row[1024];
    __shared__ float ws[TOPK];
    __shared__ int   is[TOPK];
    int t = threadIdx.x;
    for (int l = t; l < 1024; l += 256) row[l] = Vt[(size_t)bd * 1024 + l];
    if (t < TOPK) { ws[t] = w[(size_t)b * 64 + t]; is[t] = idx[t]; }
    __syncthreads();
    for (int l = t; l < 1024; l += 256) {
        float a = 0.f;
#pragma unroll
        for (int k = 0; k < TOPK; k++) a = fmaf(ws[k], row[(l + is[k]) & 1023], a);
        agg[(size_t)bd * 1024 + l] = a;
    }
}

// ---------------- context = 0.9*agg^T + 0.1*ctx_sp ----------------
__global__ void mix_k(const float* __restrict__ agg, const float* __restrict__ csp,
                      float* __restrict__ ctx)
{
    __shared__ float tile[32][33];
    int b = blockIdx.z;
    int l0 = blockIdx.x * 32, d0 = blockIdx.y * 32;
    int x = threadIdx.x, y = threadIdx.y;
#pragma unroll
    for (int i = 0; i < 32; i += 8)
        tile[y + i][x] = agg[((size_t)b * DD + d0 + y + i) * LL + l0 + x];
    __syncthreads();
#pragma unroll
    for (int i = 0; i < 32; i += 8) {
        size_t o = ((size_t)b * LL + l0 + y + i) * DD + d0 + x;
        ctx[o] = 0.9f * tile[x][y + i] + 0.1f * csp[o];
    }
}

// ---------------- LayerNorm over D=256, warp per row ----------------
__global__ void __launch_bounds__(256) ln_k(
    const float* __restrict__ in, const float* __restrict__ g,
    const float* __restrict__ b, float* __restrict__ out)
{
    const int lane = threadIdx.x & 31;
    const size_t row = (size_t)blockIdx.x * 8 + (threadIdx.x >> 5);
    const float* p = in + row * DD;
    float4 v0 = *(const float4*)&p[lane * 8];
    float4 v1 = *(const float4*)&p[lane * 8 + 4];
    float s = v0.x + v0.y + v0.z + v0.w + v1.x + v1.y + v1.z + v1.w;
#pragma unroll
    for (int off = 16; off > 0; off >>= 1)
        s += __shfl_xor_sync(0xffffffffu, s, off);
    float m = s * (1.0f / 256.0f);
    float d0x = v0.x - m, d0y = v0.y - m, d0z = v0.z - m, d0w = v0.w - m;
    float d1x = v1.x - m, d1y = v1.y - m, d1z = v1.z - m, d1w = v1.w - m;
    float vv = d0x * d0x + d0y * d0y + d0z * d0z + d0w * d0w
             + d1x * d1x + d1y * d1y + d1z * d1z + d1w * d1w;
#pragma unroll
    for (int off = 16; off > 0; off >>= 1)
        vv += __shfl_xor_sync(0xffffffffu, vv, off);
    float inv = rsqrtf(vv * (1.0f / 256.0f) + 1e-8f);
    float4 g0 = *(const float4*)&g[lane * 8];
    float4 g1 = *(const float4*)&g[lane * 8 + 4];
    float4 b0 = *(const float4*)&b[lane * 8];
    float4 b1 = *(const float4*)&b[lane * 8 + 4];
    float4 o0, o1;
    o0.x = d0x * inv * g0.x + b0.x; o0.y = d0y * inv * g0.y + b0.y;
    o0.z = d0z * inv * g0.z + b0.z; o0.w = d0w * inv * g0.w + b0.w;
    o1.x = d1x * inv * g1.x + b1.x; o1.y = d1y * inv * g1.y + b1.y;
    o1.z = d1z * inv * g1.z + b1.z; o1.w = d1w * inv * g1.w + b1.w;
    *(float4*)&out[row * DD + lane * 8] = o0;
    *(float4*)&out[row * DD + lane * 8 + 4] = o1;
}

// ---------------- launch ----------------
extern "C" void kernel_launch(void* const* d_in, const int* in_sizes, int n_in,
                              void* d_out, int out_size)
{
    const float* x   = (const float*)d_in[0];
    const float* Wq  = (const float*)d_in[1];
    const float* bq  = (const float*)d_in[2];
    const float* Wk  = (const float*)d_in[3];
    const float* bk  = (const float*)d_in[4];
    const float* Wv  = (const float*)d_in[5];
    const float* bv  = (const float*)d_in[6];
    const float* Wd  = (const float*)d_in[7];
    const float* bd  = (const float*)d_in[8];
    const float* ln1g = (const float*)d_in[9];
    const float* ln1b = (const float*)d_in[10];
    const float* W1  = (const float*)d_in[11];
    const float* b1  = (const float*)d_in[12];
    const float* W2  = (const float*)d_in[13];
    const float* b2  = (const float*)d_in[14];
    const float* ln2g = (const float*)d_in[15];
    const float* ln2b = (const float*)d_in[16];
    float* out = (float*)d_out;

    float* scr = nullptr;
    int* idxp = nullptr;
    cudaGetSymbolAddress((void**)&scr, g_scr);
    cudaGetSymbolAddress((void**)&idxp, g_idx);

    float* bQ   = scr + O_Q;   float* bK  = scr + O_K;   float* bV  = scr + O_V;
    float* Kt   = scr + O_KT;  float* Vt  = scr + O_VT;  float* trb = scr + O_TR;
    float* spK  = scr + O_SPK; float* spV = scr + O_SPV; float* spQ = scr + O_SPQ;
    float* vsb  = scr + O_VS;  float* qsb = scr + O_QS;
    float* csp  = scr + O_CSP; float* agg = scr + O_AGG; float* ctx = scr + O_CTX;
    float* t1   = scr + O_T1;  float* hb  = scr + O_H;
    float* g1b  = scr + O_G1;  float* fb  = scr + O_F;
    float* mv   = scr + O_MV;  float* wts = scr + O_W;

    const int flash_smem = (64 * 136 + 2 * 64 * 72 + 128 * 68) * sizeof(float); // 106496
    cudaFuncSetAttribute(flash_tc, cudaFuncAttributeMaxDynamicSharedMemorySize, flash_smem);
    const int fft_smem = (768 + 8 * 1056) * sizeof(float2);                      // 73728
    cudaFuncSetAttribute(fftfwd_k, cudaFuncAttributeMaxDynamicSharedMemorySize, fft_smem);
    cudaFuncSetAttribute(fftinv_k, cudaFuncAttributeMaxDynamicSharedMemorySize, fft_smem);

    const dim3 tb(32, 8);

    // 1. QKV projections — ONE launch, grid.z selects weight/bias/output
    gemm_qkv<<<dim3(2, 256, 3), 256>>>(x, Wq, bq, bQ, Wk, bk, bK, Wv, bv, bV);

    // 2. fused transposes to (B,D,L): bK->Kt, bV->Vt, bQ->trb
    tr3_k<<<dim3(8, 32, 96), tb>>>(bK, bV, bQ, Kt, Vt, trb);

    // 3. forward band FFT — ONE launch over KT|VT|TR -> SPK|SPV|SPQ
    fftfwd_k<<<3 * BB * DD / 8, 512, fft_smem>>>(Kt, spK);

    // 4. corr mean path
    corr_part_k<<<dim3(8, BB), 256>>>(spQ, spK, t1);
    meanv_k<<<dim3(BB, 4), 256>>>(t1, mv);
    topk_k<<<1, 1024>>>(mv, idxp, wts);

    // 5. inverse band FFT — ONE launch over SPV|SPQ -> VS|QS
    fftinv_k<<<2 * BB * DD / 8, 512, fft_smem>>>(spV, vsb);

    // 6. spatial attention (tf32; K = raw Kt)
    flash_tc<<<dim3(8, BB * HH), 128, flash_smem>>>(qsb, Kt, vsb, csp);

    // 7. time aggregation + mix
    timeagg_k<<<BB * DD, 256>>>(Vt, wts, idxp, agg);
    mix_k<<<dim3(32, 8, BB), tb>>>(agg, csp, ctx);

    // 8. output projection + residual + LN1
    gemm_tc<2><<<dim3(2, 256), 256>>>(ctx, Wd, bd, x, t1, BB * LL, DD, DD);
    ln_k<<<BB * LL / 8, 256>>>(t1, ln1g, ln1b, hb);

    // 9. FFN + LN2
    gemm_tc<3><<<dim3(2, 256), 256>>>(hb, W1, b1, nullptr, g1b, BB * LL, DD, DD);
    gemm_tc<2><<<dim3(2, 256), 256>>>(g1b, W2, b2, hb, fb, BB * LL, DD, DD);
    ln_k<<<BB * LL / 8, 256>>>(fb, ln2g, ln2b, out);
}